// round 1
// baseline (speedup 1.0000x reference)
#include <cuda_runtime.h>
#include <math.h>

#define S_LEN  128
#define D_DIM  25
#define E_DIM  301
#define NCLS   5
#define GN     650     // 625 bilinear cols (i*25+j) + 25 linear cols
#define PSTR   672     // padded row stride (floats), 16B-aligned
#define VOCAB_MAX 50000

// Precomputed per-vocab table:
//   cols [0,625):   Ptable[w, i*25+j] = sum_e emb[w,e]*A[i,e,j] + V[j,i]
//   cols [625,650): ctable[w, d]      = sum_e emb[w,e]*W[e,d]   + b[d]
__device__ float g_Ptable[(size_t)VOCAB_MAX * PSTR];

// ---------------------------------------------------------------------------
// GEMM: [vocab x 301] @ [301 x 650] -> g_Ptable   (fp32, tiled SGEMM)
// Bmat[e, n<625] = A[i,e,j] (n=i*25+j, stride 25 in e)
// Bmat[e, 625+d] = W[e,d]            (stride 25 in e as well)
// ---------------------------------------------------------------------------
__global__ void __launch_bounds__(256, 2)
precompute_gemm(const float* __restrict__ emb,
                const float* __restrict__ A,
                const float* __restrict__ W,
                const float* __restrict__ V,
                const float* __restrict__ bvec,
                int vocab)
{
    const int BM = 128, BN = 64, BK = 8;
    __shared__ float As[BK][BM];
    __shared__ float Bs[BK][BN];

    const int tid = threadIdx.x;
    const int m0  = blockIdx.y * BM;
    const int n0  = blockIdx.x * BN;
    const int tx  = tid & 15;     // 16 cols of threads -> 64 n
    const int ty  = tid >> 4;     // 16 rows of threads -> 128 m

    // --- A-tile (emb) load mapping: each thread loads 4 consecutive k ---
    const int am  = tid & 127;
    const int ak  = (tid >> 7) * 4;
    const int arow = m0 + am;
    const float* aptr = emb + (size_t)((arow < vocab) ? arow : 0) * E_DIM;
    const bool arow_ok = (arow < vocab);

    // --- B-tile load mapping: 2 elements per thread, both stride-25 in e ---
    // element q: linear idx = tid + q*256 -> (bk, bn)
    int   bk_[2], bn_[2];
    const float* bbase_[2];
    bool  bval_[2];
    #pragma unroll
    for (int q = 0; q < 2; ++q) {
        int idx = tid + q * 256;
        int bk = idx >> 6;         // 0..7
        int bn = idx & 63;
        int n  = n0 + bn;
        bk_[q] = bk; bn_[q] = bn;
        if (n < 625) {
            int i = n / 25, j = n % 25;
            bbase_[q] = A + (size_t)i * (E_DIM * 25) + j;
            bval_[q]  = true;
        } else if (n < GN) {
            bbase_[q] = W + (n - 625);
            bval_[q]  = true;
        } else {
            bbase_[q] = W;  // dummy
            bval_[q]  = false;
        }
    }

    float acc[8][4];
    #pragma unroll
    for (int u = 0; u < 8; ++u)
        #pragma unroll
        for (int v = 0; v < 4; ++v) acc[u][v] = 0.f;

    const int NKT = (E_DIM + BK - 1) / BK;   // 38
    for (int kt = 0; kt < NKT; ++kt) {
        const int k0 = kt * BK;

        // load A tile (transposed into As[k][m])
        #pragma unroll
        for (int u = 0; u < 4; ++u) {
            int k = k0 + ak + u;
            As[ak + u][am] = (arow_ok && k < E_DIM) ? aptr[k] : 0.f;
        }
        // load B tile
        #pragma unroll
        for (int q = 0; q < 2; ++q) {
            int e = k0 + bk_[q];
            Bs[bk_[q]][bn_[q]] = (bval_[q] && e < E_DIM) ? bbase_[q][(size_t)e * 25] : 0.f;
        }
        __syncthreads();

        #pragma unroll
        for (int kk = 0; kk < BK; ++kk) {
            const float4* a4 = (const float4*)&As[kk][ty * 8];
            float4 a0 = a4[0], a1 = a4[1];
            float4 b0 = *(const float4*)&Bs[kk][tx * 4];
            float ar[8] = {a0.x, a0.y, a0.z, a0.w, a1.x, a1.y, a1.z, a1.w};
            float br[4] = {b0.x, b0.y, b0.z, b0.w};
            #pragma unroll
            for (int u = 0; u < 8; ++u)
                #pragma unroll
                for (int v = 0; v < 4; ++v)
                    acc[u][v] = fmaf(ar[u], br[v], acc[u][v]);
        }
        __syncthreads();
    }

    // epilogue: fold V (bilinear cols) / bias b (linear cols), store
    #pragma unroll
    for (int u = 0; u < 8; ++u) {
        int row = m0 + ty * 8 + u;
        if (row >= vocab) continue;
        float* orow = g_Ptable + (size_t)row * PSTR;
        #pragma unroll
        for (int v = 0; v < 4; ++v) {
            int n = n0 + tx * 4 + v;
            if (n >= GN) continue;
            float add = (n < 625) ? V[(n % 25) * 25 + (n / 25)] : bvec[n - 625];
            orow[n] = acc[u][v] + add;
        }
    }
}

// ---------------------------------------------------------------------------
// Recurrence: one warp per batch element, loops t=0..127.
//   h_new[i] = tanh( c[i] + sum_j (P[i,j]) * h[j] )   (V, b already folded)
// Final head: sigmoid(h @ out_W^T + out_b) fused.
// ---------------------------------------------------------------------------
__global__ void __launch_bounds__(256)
recurrence_kernel(const int* __restrict__ words,
                  const float* __restrict__ outW,
                  const float* __restrict__ outb,
                  float* __restrict__ out,
                  int B)
{
    const int WPB = 8;
    __shared__ float Pbuf[WPB][PSTR];
    __shared__ float hs[WPB][32];

    const int lane = threadIdx.x & 31;
    const int w    = threadIdx.x >> 5;
    const int b    = blockIdx.x * WPB + w;
    if (b >= B) return;    // uniform per warp

    const int* wrow = words + (size_t)b * S_LEN;
    float* pb = Pbuf[w];
    float* hb = hs[w];

    hb[lane] = (lane == D_DIM - 1) ? 1.f : 0.f;
    __syncwarp();

    for (int t = 0; t < S_LEN; ++t) {
        const int word = wrow[t];
        const float4* src = (const float4*)(g_Ptable + (size_t)word * PSTR);
        float4* dst = (float4*)pb;
        #pragma unroll
        for (int q = lane; q < 163; q += 32)   // 163*4 = 652 >= 650 floats
            dst[q] = src[q];
        __syncwarp();

        float hn = 0.f;
        if (lane < D_DIM) {
            float acc = pb[625 + lane];                  // c (incl. bias)
            const float* prow = pb + lane * D_DIM;       // P row i (incl. V)
            #pragma unroll
            for (int j = 0; j < D_DIM; ++j)
                acc = fmaf(prow[j], hb[j], acc);
            hn = tanhf(acc);
        }
        __syncwarp();
        if (lane < D_DIM) hb[lane] = hn;
        __syncwarp();
    }

    if (lane < NCLS) {
        float acc = outb[lane];
        #pragma unroll
        for (int i = 0; i < D_DIM; ++i)
            acc = fmaf(outW[lane * D_DIM + i], hb[i], acc);
        out[(size_t)b * NCLS + lane] = 1.f / (1.f + expf(-acc));
    }
}

// ---------------------------------------------------------------------------
extern "C" void kernel_launch(void* const* d_in, const int* in_sizes, int n_in,
                              void* d_out, int out_size)
{
    // inputs (metadata order): words, batch_size, emb_table, A, W, V, b, out_W, out_b
    // tolerate a missing batch_size scalar
    const int o = (n_in >= 9) ? 1 : 0;
    const int*   words = (const int*)  d_in[0];
    const float* emb   = (const float*)d_in[1 + o];
    const float* A     = (const float*)d_in[2 + o];
    const float* W     = (const float*)d_in[3 + o];
    const float* V     = (const float*)d_in[4 + o];
    const float* bvec  = (const float*)d_in[5 + o];
    const float* outW  = (const float*)d_in[6 + o];
    const float* outb  = (const float*)d_in[7 + o];
    float* out = (float*)d_out;

    const int B     = in_sizes[0] / S_LEN;
    int vocab       = in_sizes[1 + o] / E_DIM;
    if (vocab > VOCAB_MAX) vocab = VOCAB_MAX;

    // 1) precompute per-vocab table
    dim3 ggrid((GN + 63) / 64, (vocab + 127) / 128);
    precompute_gemm<<<ggrid, 256>>>(emb, A, W, V, bvec, vocab);

    // 2) recurrence + head
    const int WPB = 8;
    int rblocks = (B + WPB - 1) / WPB;
    recurrence_kernel<<<rblocks, WPB * 32>>>(words, outW, outb, out, B);
}